// round 1
// baseline (speedup 1.0000x reference)
#include <cuda_runtime.h>
#include <stdint.h>

#define NANCH 8732
#define NCLS 21
#define TOPK 200
#define CONF_TH 0.01f
#define NMS_TH 0.045f
#define MAXB 128

// Scratch (no device allocs allowed):
__device__ float g_probsT[(size_t)MAXB * NCLS * NANCH];   // masked softmax probs, [B,C,N]
__device__ float g_boxes[(size_t)MAXB * NANCH * 4];       // decoded corner boxes, [B,N,4]

// ---------------------------------------------------------------------------
// Kernel A: softmax over classes + SSD box decode. One thread per (b,n).
// ---------------------------------------------------------------------------
__global__ void softmax_decode_kernel(const float* __restrict__ loc,
                                      const float* __restrict__ conf,
                                      const float* __restrict__ anchors,
                                      int B) {
    int idx = blockIdx.x * blockDim.x + threadIdx.x;
    if (idx >= B * NANCH) return;
    int b = idx / NANCH;
    int n = idx - b * NANCH;

    const float* cp = conf + (size_t)idx * NCLS;
    float v[NCLS];
    float mx = -1e30f;
#pragma unroll
    for (int c = 0; c < NCLS; c++) { v[c] = cp[c]; mx = fmaxf(mx, v[c]); }
    float s = 0.0f;
#pragma unroll
    for (int c = 0; c < NCLS; c++) { v[c] = expf(v[c] - mx); s += v[c]; }
    float inv = 1.0f / s;
#pragma unroll
    for (int c = 0; c < NCLS; c++) {
        float p = v[c] * inv;
        // mask: exactly 0 when <= threshold (matches jnp.where)
        g_probsT[((size_t)b * NCLS + c) * NANCH + n] = (p > CONF_TH) ? p : 0.0f;
    }

    const float* lp = loc + (size_t)idx * 4;
    const float* ap = anchors + (size_t)n * 4;
    float a0 = ap[0], a1 = ap[1], a2 = ap[2], a3 = ap[3];
    float cx = a0 + lp[0] * 0.1f * a2;
    float cy = a1 + lp[1] * 0.1f * a3;
    float w  = a2 * expf(lp[2] * 0.2f);
    float h  = a3 * expf(lp[3] * 0.2f);
    float* bp = g_boxes + (size_t)idx * 4;
    bp[0] = cx - 0.5f * w;
    bp[1] = cy - 0.5f * h;
    bp[2] = cx + 0.5f * w;
    bp[3] = cy + 0.5f * h;
}

// ---------------------------------------------------------------------------
// Kernel B: per (b, class) task — radix-select top-200, bitonic sort
// (value desc, idx asc — JAX top_k tie-break), serial NMS, packed write.
// One CTA of 256 threads per task.
// ---------------------------------------------------------------------------
__global__ void __launch_bounds__(256) topk_nms_kernel(float* __restrict__ out) {
    int task = blockIdx.x;
    int b = task / (NCLS - 1);
    int c = task % (NCLS - 1) + 1;   // skip background class 0
    int tid = threadIdx.x;

    __shared__ unsigned sbits[NANCH];           // score bits (order == value order, all >= 0)
    __shared__ unsigned hist[256];
    __shared__ unsigned sfx[256];
    __shared__ unsigned long long skey[256];    // (vbits<<32) | ~idx
    __shared__ float sbx[TOPK][4];
    __shared__ float sarea[TOPK];
    __shared__ int skeep[TOPK];
    __shared__ unsigned k_sh, bin_sh, cnt_sh;
    __shared__ unsigned wcnt[8], woff[8];

    // Load masked scores (coalesced: [B,C,N] layout).
    const float* sp = g_probsT + ((size_t)b * NCLS + c) * NANCH;
    for (int n = tid; n < NANCH; n += 256)
        sbits[n] = __float_as_uint(sp[n]);
    if (tid == 0) { k_sh = TOPK; cnt_sh = 0u; }
    skey[tid] = 0ULL;
    __syncthreads();

    // --- 4-pass radix select: find bit pattern P of the 200th largest ---
    unsigned prefix = 0u, pmask = 0u;
#pragma unroll
    for (int pass = 0; pass < 4; pass++) {
        int shift = 24 - 8 * pass;
        hist[tid] = 0u;
        __syncthreads();
        for (int n = tid; n < NANCH; n += 256) {
            unsigned u = sbits[n];
            if ((u & pmask) == prefix) atomicAdd(&hist[(u >> shift) & 255u], 1u);
        }
        __syncthreads();
        // reverse (suffix) inclusive scan over 256 bins, Hillis-Steele
        sfx[tid] = hist[tid];
        __syncthreads();
        for (int off = 1; off < 256; off <<= 1) {
            unsigned v = (tid + off < 256) ? sfx[tid + off] : 0u;
            __syncthreads();
            sfx[tid] += v;
            __syncthreads();
        }
        unsigned kcur = k_sh;
        unsigned s_here = sfx[tid];
        unsigned s_next = (tid < 255) ? sfx[tid + 1] : 0u;
        __syncthreads();
        if (s_here >= kcur && s_next < kcur) {   // unique thread (sfx non-increasing)
            bin_sh = (unsigned)tid;
            k_sh = kcur - s_next;                // ties at pivot still needed
        }
        __syncthreads();
        prefix |= bin_sh << shift;
        pmask  |= 255u << shift;
    }
    unsigned P = prefix;
    // If P==0 (<200 positive scores), padding rows are score-0 => never kept,
    // never suppress, never written. So collect strictly-positive only.
    unsigned Plo = (P > 0u) ? P : 1u;

    // --- collect candidates >= pivot (m strictly greater + all ties; <=256) ---
    for (int n = tid; n < NANCH; n += 256) {
        unsigned u = sbits[n];
        if (u >= Plo) {
            unsigned p = atomicAdd(&cnt_sh, 1u);
            if (p < 256u)
                skey[p] = ((unsigned long long)u << 32) | (unsigned)(~n);
        }
    }
    __syncthreads();

    // --- bitonic sort 256 keys, descending => value desc, idx asc on ties ---
#pragma unroll
    for (int ks = 2; ks <= 256; ks <<= 1) {
        for (int st = ks >> 1; st > 0; st >>= 1) {
            int partner = tid ^ st;
            if (partner > tid) {
                bool desc = ((tid & ks) == 0);
                unsigned long long a = skey[tid], bb = skey[partner];
                bool sw = desc ? (a < bb) : (a > bb);
                if (sw) { skey[tid] = bb; skey[partner] = a; }
            }
            __syncthreads();
        }
    }

    // --- fetch boxes for selected top-200 ---
    float score = 0.f, x1 = 0.f, y1 = 0.f, x2 = 0.f, y2 = 0.f, area = 0.f;
    int keepf = 0;
    if (tid < TOPK) {
        unsigned long long key = skey[tid];
        unsigned vb = (unsigned)(key >> 32);
        if (vb != 0u) {
            unsigned n = ~(unsigned)(key & 0xFFFFFFFFu);
            score = __uint_as_float(vb);       // > CONF_TH by construction
            const float* bp = g_boxes + (((size_t)b * NANCH) + n) * 4;
            x1 = bp[0]; y1 = bp[1]; x2 = bp[2]; y2 = bp[3];
            area = (x2 - x1) * (y2 - y1);
            keepf = 1;
        }
        sbx[tid][0] = x1; sbx[tid][1] = y1; sbx[tid][2] = x2; sbx[tid][3] = y2;
        sarea[tid] = area;
        skeep[tid] = keepf;
    }
    __syncthreads();

    // --- serial greedy NMS (exactly the reference fori_loop semantics) ---
    for (int i = 0; i < TOPK - 1; i++) {
        if (tid > i && tid < TOPK && keepf && skeep[i]) {
            float ix1 = fmaxf(x1, sbx[i][0]);
            float iy1 = fmaxf(y1, sbx[i][1]);
            float ix2 = fminf(x2, sbx[i][2]);
            float iy2 = fminf(y2, sbx[i][3]);
            float iw = fmaxf(ix2 - ix1, 0.0f);
            float ih = fmaxf(iy2 - iy1, 0.0f);
            float inter = iw * ih;
            float iou = inter / (area + sarea[i] - inter + 1e-12f);
            if (iou > NMS_TH) { keepf = 0; skeep[tid] = 0; }
        }
        __syncthreads();
    }

    // --- pack kept entries to the front (stable), write output ---
    int lane = tid & 31, wrp = tid >> 5;
    unsigned bal = __ballot_sync(0xffffffffu, keepf);
    if (lane == 0) wcnt[wrp] = __popc(bal);
    __syncthreads();
    if (tid == 0) {
        unsigned run = 0;
        for (int i = 0; i < 8; i++) { woff[i] = run; run += wcnt[i]; }
    }
    __syncthreads();
    if (keepf) {
        int pos = woff[wrp] + __popc(bal & ((1u << lane) - 1u));
        float* orow = out + ((((size_t)b * NCLS + c) * TOPK) + pos) * 5;
        orow[0] = score; orow[1] = x1; orow[2] = y1; orow[3] = x2; orow[4] = y2;
    }
}

// ---------------------------------------------------------------------------
extern "C" void kernel_launch(void* const* d_in, const int* in_sizes, int n_in,
                              void* d_out, int out_size) {
    const float* loc     = (const float*)d_in[0];  // [B,N,4]
    const float* conf    = (const float*)d_in[1];  // [B,N,21]
    const float* anchors = (const float*)d_in[2];  // [N,4]
    float* out = (float*)d_out;                    // [B,21,200,5]

    int B = in_sizes[0] / (NANCH * 4);
    if (B > MAXB) B = MAXB;

    // zero output (non-kept rows + background class stay zero)
    cudaMemsetAsync(d_out, 0, (size_t)out_size * sizeof(float), 0);

    int total = B * NANCH;
    softmax_decode_kernel<<<(total + 255) / 256, 256>>>(loc, conf, anchors, B);
    topk_nms_kernel<<<B * (NCLS - 1), 256>>>(out);
}